// round 13
// baseline (speedup 1.0000x reference)
#include <cuda_runtime.h>
#include <float.h>

#define BT     (16 * 512)   // 8192 pairs
#define IDIM   80
#define HDIM   512
#define NSHIFT 159
#define PAD    79
#define SKP    248

#define NGROUP 64            // 128 pairs per group
#define CTAS_PER_GROUP 20    // 16 attn + 4 gemm
#define SP2    44            // gemm smem uint stride (R11-validated)

// Scratch (allocation-free rule: __device__ globals)
__device__ float g_xattn[BT * IDIM];
__device__ int   g_cnt[NGROUP];

__device__ __forceinline__ float warpReduceSum(float v) {
#pragma unroll
    for (int o = 16; o; o >>= 1) v += __shfl_xor_sync(0xffffffffu, v, o);
    return v;
}
__device__ __forceinline__ float warpReduceMax(float v) {
#pragma unroll
    for (int o = 16; o; o >>= 1) v = fmaxf(v, __shfl_xor_sync(0xffffffffu, v, o));
    return v;
}

__device__ __forceinline__ unsigned f16pack(float v0, float v1) {
    unsigned r;
    asm("cvt.rn.f16x2.f32 %0, %1, %2;" : "=r"(r) : "f"(v1), "f"(v0));
    return r;
}

__device__ __forceinline__ void mma_f16(float d[4],
                                        unsigned a0, unsigned a1,
                                        unsigned a2, unsigned a3,
                                        unsigned b0, unsigned b1) {
    asm("mma.sync.aligned.m16n8k16.row.col.f32.f16.f16.f32 "
        "{%0,%1,%2,%3}, {%4,%5,%6,%7}, {%8,%9}, {%0,%1,%2,%3};"
        : "+f"(d[0]), "+f"(d[1]), "+f"(d[2]), "+f"(d[3])
        : "r"(a0), "r"(a1), "r"(a2), "r"(a3), "r"(b0), "r"(b1));
}

// attn per-warp smem: kp[248] + ys[80] = 328 floats
#define AW 328

__global__ __launch_bounds__(256, 2) void fused_kernel(
    const float* __restrict__ x, const float* __restrict__ y,
    const float* __restrict__ W, const float* __restrict__ bias,
    float* __restrict__ out)
{
    extern __shared__ float smem_f[];
    const int bid = blockIdx.x;
    const int g   = bid / CTAS_PER_GROUP;
    const int r   = bid % CTAS_PER_GROUP;
    const int tid = threadIdx.x;
    const int warp = tid >> 5;
    const int lane = tid & 31;

    if (r < 16) {
        // ================== ATTN CTA (R11-validated, 8 pairs) ==============
        const int p = (g * 16 + r) * 8 + warp;
        float* kpw = smem_f + warp * AW;
        float* ysw = kpw + SKP;

        for (int i = lane; i < SKP; i += 32) kpw[i] = 0.0f;
        __syncwarp();

        const float* xp = x + (size_t)p * IDIM;
        const float* yp = y + (size_t)p * IDIM;
        float yn2 = 0.0f;
        for (int i = lane; i < IDIM; i += 32) {
            kpw[PAD + i] = xp[i];
            float v = yp[i];
            ysw[i] = v;
            yn2 = fmaf(v, v, yn2);
        }
        yn2 = warpReduceSum(yn2);
        __syncwarp();

        const int base = lane * 5;
        float w0 = kpw[base + 0], w1 = kpw[base + 1], w2 = kpw[base + 2],
              w3 = kpw[base + 3], w4 = kpw[base + 4];
        const float i0 = w0, i1 = w1, i2 = w2, i3 = w3;

        float d0 = 0, d1 = 0, d2 = 0, d3 = 0, d4 = 0, core = 0;
#pragma unroll
        for (int i = 0; i < IDIM; ++i) {
            float yv = ysw[i];
            d0 = fmaf(w0, yv, d0);
            d1 = fmaf(w1, yv, d1);
            d2 = fmaf(w2, yv, d2);
            d3 = fmaf(w3, yv, d3);
            d4 = fmaf(w4, yv, d4);
            if (i < IDIM - 4) core = fmaf(w4, w4, core);
            w0 = w1; w1 = w2; w2 = w3; w3 = w4;
            w4 = kpw[base + 5 + i];
        }

        const float t0 = kpw[base + 80], t1 = kpw[base + 81],
                    t2 = kpw[base + 82], t3 = kpw[base + 83];
        const float H3 = i3 * i3;
        const float H2 = fmaf(i2, i2, H3);
        const float H1 = fmaf(i1, i1, H2);
        const float H0 = fmaf(i0, i0, H1);
        const float T1 = t0 * t0;
        const float T2 = fmaf(t1, t1, T1);
        const float T3 = fmaf(t2, t2, T2);
        const float T4 = fmaf(t3, t3, T3);

        float dotv[5] = {d0, d1, d2, d3, d4};
        float n2v[5];
        n2v[0] = H0 + core;
        n2v[1] = (H1 + core) + T1;
        n2v[2] = (H2 + core) + T2;
        n2v[3] = (H3 + core) + T3;
        n2v[4] = core + T4;

        const float yn = sqrtf(yn2);
        float best = -FLT_MAX;
        int   bidx = 0;
#pragma unroll
        for (int j = 0; j < 5; ++j) {
            int s = base + j;
            if (s < NSHIFT) {
                float den = sqrtf(n2v[j]) * yn;
                float sim = (den > 0.0f) ? (dotv[j] / den) : 0.0f;
                if (sim > best) { best = sim; bidx = s; }
            }
        }
#pragma unroll
        for (int o = 16; o; o >>= 1) {
            float ov = __shfl_xor_sync(0xffffffffu, best, o);
            int   oi = __shfl_xor_sync(0xffffffffu, bidx, o);
            if (ov > best || (ov == best && oi < bidx)) { best = ov; bidx = oi; }
        }
        const int bs = bidx;

        float xa[3], sc[3];
        float m = -FLT_MAX;
#pragma unroll
        for (int t = 0; t < 3; ++t) {
            int i = lane + t * 32;
            if (i < IDIM) {
                xa[t] = kpw[bs + i];
                sc[t] = xa[t] * ysw[i];
                m = fmaxf(m, sc[t]);
            }
        }
        m = warpReduceMax(m);
        float sum = 0.0f, e[3];
#pragma unroll
        for (int t = 0; t < 3; ++t) {
            int i = lane + t * 32;
            if (i < IDIM) { e[t] = expf((sc[t] - m) * 0.1f); sum += e[t]; }
        }
        sum = warpReduceSum(sum);
        const float inv = 1.0f / sum;
#pragma unroll
        for (int t = 0; t < 3; ++t) {
            int i = lane + t * 32;
            if (i < IDIM) g_xattn[(size_t)p * IDIM + i] = xa[t] * (e[t] * inv);
        }

        // publish: all 8 pairs of this CTA written
        __syncthreads();
        __threadfence();
        if (tid == 0) atomicAdd(&g_cnt[g], 1);

    } else {
        // ================== GEMM CTA (R11-validated fp16 mma) ==============
        // wait for this group's 16 producers
        if (tid == 0) {
            volatile int* c = &g_cnt[g];
            while (*c < 16) __nanosleep(128);
        }
        __syncthreads();
        __threadfence();   // acquire: order xattn reads after flag

        unsigned* As = reinterpret_cast<unsigned*>(smem_f);
        unsigned* Bs = As + 128 * SP2;
        const float* A = g_xattn;

        const int bm = g * 128;
        const int bn = (r - 16) * 128;
        const int wm = warp >> 2;
        const int wn = warp & 3;
        const int gq = lane >> 2;
        const int t  = lane & 3;

#pragma unroll
        for (int it = 0; it < 10; ++it) {
            int idx = tid + it * 256;
            int row = idx / 20;
            int k4  = (idx % 20) * 4;
            int c   = k4 >> 1;

            float4 a = *reinterpret_cast<const float4*>(A + (size_t)(bm + row) * IDIM + k4);
            *reinterpret_cast<uint2*>(&As[row * SP2 + c]) =
                make_uint2(f16pack(a.x, a.y), f16pack(a.z, a.w));

            float4 b = *reinterpret_cast<const float4*>(W + (size_t)(bn + row) * IDIM + k4);
            *reinterpret_cast<uint2*>(&Bs[row * SP2 + c]) =
                make_uint2(f16pack(b.x, b.y), f16pack(b.z, b.w));
        }
        __syncthreads();

        float d[4][4][4];
#pragma unroll
        for (int mt = 0; mt < 4; ++mt)
#pragma unroll
            for (int nt = 0; nt < 4; ++nt)
#pragma unroll
                for (int q = 0; q < 4; ++q) d[mt][nt][q] = 0.0f;

#pragma unroll
        for (int kc = 0; kc < 5; ++kc) {
            const int kb = kc * 8 + t;

            unsigned b0[4], b1[4];
#pragma unroll
            for (int nt = 0; nt < 4; ++nt) {
                int nr = (wn * 32 + nt * 8 + gq) * SP2 + kb;
                b0[nt] = Bs[nr];
                b1[nt] = Bs[nr + 4];
            }

#pragma unroll
            for (int mt = 0; mt < 4; ++mt) {
                int r0 = (wm * 64 + mt * 16 + gq) * SP2 + kb;
                unsigned a0 = As[r0];
                unsigned a1 = As[r0 + 8 * SP2];
                unsigned a2 = As[r0 + 4];
                unsigned a3 = As[r0 + 8 * SP2 + 4];
#pragma unroll
                for (int nt = 0; nt < 4; ++nt)
                    mma_f16(d[mt][nt], a0, a1, a2, a3, b0[nt], b1[nt]);
            }
        }

#pragma unroll
        for (int mt = 0; mt < 4; ++mt) {
#pragma unroll
            for (int nt = 0; nt < 4; ++nt) {
                int row = bm + wm * 64 + mt * 16 + gq;
                int col = bn + wn * 32 + nt * 8 + 2 * t;
                float b0 = __ldg(bias + col), b1 = __ldg(bias + col + 1);
                float2 o0 = make_float2(d[mt][nt][0] + b0, d[mt][nt][1] + b1);
                float2 o1 = make_float2(d[mt][nt][2] + b0, d[mt][nt][3] + b1);
                *reinterpret_cast<float2*>(out + (size_t)row * HDIM + col) = o0;
                *reinterpret_cast<float2*>(out + (size_t)(row + 8) * HDIM + col) = o1;
            }
        }
    }
}

extern "C" void kernel_launch(void* const* d_in, const int* in_sizes, int n_in,
                              void* d_out, int out_size)
{
    const float* x    = (const float*)d_in[0];
    const float* y    = (const float*)d_in[1];
    const float* fc1w = (const float*)d_in[2];
    const float* fc1b = (const float*)d_in[3];
    float* out = (float*)d_out;

    void* cnt = nullptr;
    cudaGetSymbolAddress(&cnt, g_cnt);
    cudaMemsetAsync(cnt, 0, NGROUP * sizeof(int));

    const int smem_bytes = 2 * 128 * SP2 * (int)sizeof(unsigned);  // 45056
    cudaFuncSetAttribute(fused_kernel,
                         cudaFuncAttributeMaxDynamicSharedMemorySize, smem_bytes);
    fused_kernel<<<NGROUP * CTAS_PER_GROUP, 256, smem_bytes>>>(
        x, y, fc1w, fc1b, out);
}

// round 14
// speedup vs baseline: 1.6183x; 1.6183x over previous
#include <cuda_runtime.h>
#include <float.h>

#define BT     (16 * 512)   // 8192 pairs
#define IDIM   80
#define HDIM   512
#define NSHIFT 159
#define PAD    79
#define SKP    248

// Scratch: x_attn stored as fp16 bits (allocation-free rule: __device__ global)
__device__ unsigned short g_xattn_h[BT * IDIM];

__device__ __forceinline__ float warpReduceSum(float v) {
#pragma unroll
    for (int o = 16; o; o >>= 1) v += __shfl_xor_sync(0xffffffffu, v, o);
    return v;
}
__device__ __forceinline__ float warpReduceMax(float v) {
#pragma unroll
    for (int o = 16; o; o >>= 1) v = fmaxf(v, __shfl_xor_sync(0xffffffffu, v, o));
    return v;
}

// ---------------------------------------------------------------------------
// Kernel 1 (R11-validated numerics; output stored as fp16 via the SAME
// cvt.rn.f16.f32 the GEMM fill used -> bit-identical GEMM inputs).
// ---------------------------------------------------------------------------
#define PAIRS_PER_BLK 8
__global__ __launch_bounds__(256) void attn_kernel(
    const float* __restrict__ x, const float* __restrict__ y,
    unsigned short* __restrict__ xattn_h)
{
    const int warp = threadIdx.x >> 5;
    const int lane = threadIdx.x & 31;
    const int p    = blockIdx.x * PAIRS_PER_BLK + warp;

    __shared__ float kp[PAIRS_PER_BLK][SKP];
    __shared__ float ys[PAIRS_PER_BLK][IDIM];
    float* kpw = kp[warp];
    float* ysw = ys[warp];

    for (int i = lane; i < SKP; i += 32) kpw[i] = 0.0f;
    __syncwarp();

    const float* xp = x + (size_t)p * IDIM;
    const float* yp = y + (size_t)p * IDIM;
    float yn2 = 0.0f;
    for (int i = lane; i < IDIM; i += 32) {
        kpw[PAD + i] = xp[i];
        float v = yp[i];
        ysw[i] = v;
        yn2 = fmaf(v, v, yn2);
    }
    yn2 = warpReduceSum(yn2);
    __syncwarp();

    const int base = lane * 5;
    float w0 = kpw[base + 0], w1 = kpw[base + 1], w2 = kpw[base + 2],
          w3 = kpw[base + 3], w4 = kpw[base + 4];
    const float i0 = w0, i1 = w1, i2 = w2, i3 = w3;

    float d0 = 0, d1 = 0, d2 = 0, d3 = 0, d4 = 0, core = 0;
#pragma unroll
    for (int i = 0; i < IDIM; ++i) {
        float yv = ysw[i];
        d0 = fmaf(w0, yv, d0);
        d1 = fmaf(w1, yv, d1);
        d2 = fmaf(w2, yv, d2);
        d3 = fmaf(w3, yv, d3);
        d4 = fmaf(w4, yv, d4);
        if (i < IDIM - 4) core = fmaf(w4, w4, core);
        w0 = w1; w1 = w2; w2 = w3; w3 = w4;
        w4 = kpw[base + 5 + i];
    }

    const float t0 = kpw[base + 80], t1 = kpw[base + 81],
                t2 = kpw[base + 82], t3 = kpw[base + 83];
    const float H3 = i3 * i3;
    const float H2 = fmaf(i2, i2, H3);
    const float H1 = fmaf(i1, i1, H2);
    const float H0 = fmaf(i0, i0, H1);
    const float T1 = t0 * t0;
    const float T2 = fmaf(t1, t1, T1);
    const float T3 = fmaf(t2, t2, T2);
    const float T4 = fmaf(t3, t3, T3);

    float dotv[5] = {d0, d1, d2, d3, d4};
    float n2v[5];
    n2v[0] = H0 + core;
    n2v[1] = (H1 + core) + T1;
    n2v[2] = (H2 + core) + T2;
    n2v[3] = (H3 + core) + T3;
    n2v[4] = core + T4;

    const float yn = sqrtf(yn2);
    float best = -FLT_MAX;
    int   bidx = 0;
#pragma unroll
    for (int j = 0; j < 5; ++j) {
        int s = base + j;
        if (s < NSHIFT) {
            float den = sqrtf(n2v[j]) * yn;
            float sim = (den > 0.0f) ? (dotv[j] / den) : 0.0f;
            if (sim > best) { best = sim; bidx = s; }
        }
    }
#pragma unroll
    for (int o = 16; o; o >>= 1) {
        float ov = __shfl_xor_sync(0xffffffffu, best, o);
        int   oi = __shfl_xor_sync(0xffffffffu, bidx, o);
        if (ov > best || (ov == best && oi < bidx)) { best = ov; bidx = oi; }
    }
    const int bs = bidx;

    float xa[3], sc[3];
    float m = -FLT_MAX;
#pragma unroll
    for (int t = 0; t < 3; ++t) {
        int i = lane + t * 32;
        if (i < IDIM) {
            xa[t] = kpw[bs + i];
            sc[t] = xa[t] * ysw[i];
            m = fmaxf(m, sc[t]);
        }
    }
    m = warpReduceMax(m);
    float sum = 0.0f, e[3];
#pragma unroll
    for (int t = 0; t < 3; ++t) {
        int i = lane + t * 32;
        if (i < IDIM) { e[t] = expf((sc[t] - m) * 0.1f); sum += e[t]; }
    }
    sum = warpReduceSum(sum);
    const float inv = 1.0f / sum;
#pragma unroll
    for (int t = 0; t < 3; ++t) {
        int i = lane + t * 32;
        if (i < IDIM) {
            float v = xa[t] * (e[t] * inv);
            unsigned short h;
            asm("cvt.rn.f16.f32 %0, %1;" : "=h"(h) : "f"(v));
            xattn_h[(size_t)p * IDIM + i] = h;
        }
    }
}

// ---------------------------------------------------------------------------
// Kernel 2: out[8192,512] = xattn[8192,80] @ W[512,80]^T + bias
// fp16 mma.m16n8k16 (R11-validated). R14: ldmatrix fragment loads
// (conflict-free with row stride 44 uints) + fp16 A tile copied directly.
// Block 128x128, 8 warps (2x4), warp tile 64x32.
// ---------------------------------------------------------------------------
#define SP2 44   // uint stride per row

__device__ __forceinline__ unsigned f16pack(float v0, float v1) {
    unsigned r;
    asm("cvt.rn.f16x2.f32 %0, %1, %2;" : "=r"(r) : "f"(v1), "f"(v0));
    return r;
}

__device__ __forceinline__ void mma_f16(float d[4],
                                        unsigned a0, unsigned a1,
                                        unsigned a2, unsigned a3,
                                        unsigned b0, unsigned b1) {
    asm("mma.sync.aligned.m16n8k16.row.col.f32.f16.f16.f32 "
        "{%0,%1,%2,%3}, {%4,%5,%6,%7}, {%8,%9}, {%0,%1,%2,%3};"
        : "+f"(d[0]), "+f"(d[1]), "+f"(d[2]), "+f"(d[3])
        : "r"(a0), "r"(a1), "r"(a2), "r"(a3), "r"(b0), "r"(b1));
}

__device__ __forceinline__ void ldsm_x4(unsigned& r0, unsigned& r1,
                                        unsigned& r2, unsigned& r3,
                                        unsigned addr) {
    asm volatile("ldmatrix.sync.aligned.m8n8.x4.shared.b16 {%0,%1,%2,%3}, [%4];"
                 : "=r"(r0), "=r"(r1), "=r"(r2), "=r"(r3) : "r"(addr));
}

__global__ __launch_bounds__(256, 2) void gemm_kernel(
    const unsigned short* __restrict__ Ah, const float* __restrict__ W,
    const float* __restrict__ bias, float* __restrict__ out)
{
    extern __shared__ unsigned smem_u[];
    unsigned* As = smem_u;              // [128][SP2] fp16x2 (k-pair major)
    unsigned* Bs = smem_u + 128 * SP2;

    const int bn  = blockIdx.x * 128;
    const int bm  = blockIdx.y * 128;
    const int tid = threadIdx.x;
    const int warp = tid >> 5, lane = tid & 31;
    const int wm = warp >> 2;       // 0..1
    const int wn = warp & 3;        // 0..3
    const int g  = lane >> 2;
    const int t  = lane & 3;

    // Fill A: fp16 rows copied raw. 128 rows x 10 uint4 = 1280 / 256 = 5 each
#pragma unroll
    for (int it = 0; it < 5; ++it) {
        int idx = tid + it * 256;
        int row = idx / 10;
        int c4  = (idx % 10) * 4;   // uint offset within row
        uint4 a = *reinterpret_cast<const uint4*>(
            Ah + (size_t)(bm + row) * IDIM + c4 * 2);
        *reinterpret_cast<uint4*>(&As[row * SP2 + c4]) = a;
    }
    // Fill B: 128 rows x 20 float4 = 2560 / 256 = 10 each (cvt to fp16)
#pragma unroll
    for (int it = 0; it < 10; ++it) {
        int idx = tid + it * 256;
        int row = idx / 20;
        int k4  = (idx % 20) * 4;
        int c   = k4 >> 1;
        float4 b = *reinterpret_cast<const float4*>(W + (size_t)(bn + row) * IDIM + k4);
        *reinterpret_cast<uint2*>(&Bs[row * SP2 + c]) =
            make_uint2(f16pack(b.x, b.y), f16pack(b.z, b.w));
    }
    __syncthreads();

    // ldmatrix lane addresses (byte offsets advance 32B per k-chunk)
    // A, per mt: matrices {rows0-7 k0-7},{rows8-15 k0-7},{rows0-7 k8-15},{rows8-15 k8-15}
    unsigned a_addr[4];
#pragma unroll
    for (int mt = 0; mt < 4; ++mt) {
        int row = wm * 64 + mt * 16 + (lane & 7) + ((lane >> 3) & 1) * 8;
        int uoff = row * SP2 + (lane >> 4) * 4;
        a_addr[mt] = (unsigned)__cvta_generic_to_shared(As + uoff);
    }
    // B, per nt-pair j: matrices {n0-7 k0-7},{n0-7 k8-15},{n8-15 k0-7},{n8-15 k8-15}
    unsigned b_addr[2];
#pragma unroll
    for (int j = 0; j < 2; ++j) {
        int row = wn * 32 + j * 16 + (lane & 7) + ((lane >> 4) & 1) * 8;
        int uoff = row * SP2 + ((lane >> 3) & 1) * 4;
        b_addr[j] = (unsigned)__cvta_generic_to_shared(Bs + uoff);
    }

    float d[4][4][4];
#pragma unroll
    for (int mt = 0; mt < 4; ++mt)
#pragma unroll
        for (int nt = 0; nt < 4; ++nt)
#pragma unroll
            for (int r = 0; r < 4; ++r) d[mt][nt][r] = 0.0f;

    // K = 80 -> 5 chunks of k16
#pragma unroll
    for (int kc = 0; kc < 5; ++kc) {
        const unsigned koff = kc * 32;   // bytes: 8 uints per chunk

        unsigned b0[4], b1[4];
        ldsm_x4(b0[0], b1[0], b0[1], b1[1], b_addr[0] + koff);
        ldsm_x4(b0[2], b1[2], b0[3], b1[3], b_addr[1] + koff);

#pragma unroll
        for (int mt = 0; mt < 4; ++mt) {
            unsigned a0, a1, a2, a3;
            ldsm_x4(a0, a1, a2, a3, a_addr[mt] + koff);
#pragma unroll
            for (int nt = 0; nt < 4; ++nt)
                mma_f16(d[mt][nt], a0, a1, a2, a3, b0[nt], b1[nt]);
        }
    }

    // Epilogue: c0,c1 -> (row, 2t..2t+1); c2,c3 -> (row+8, 2t..2t+1)
#pragma unroll
    for (int mt = 0; mt < 4; ++mt) {
#pragma unroll
        for (int nt = 0; nt < 4; ++nt) {
            int row = bm + wm * 64 + mt * 16 + g;
            int col = bn + wn * 32 + nt * 8 + 2 * t;
            float b0 = __ldg(bias + col), b1 = __ldg(bias + col + 1);
            float2 o0 = make_float2(d[mt][nt][0] + b0, d[mt][nt][1] + b1);
            float2 o1 = make_float2(d[mt][nt][2] + b0, d[mt][nt][3] + b1);
            *reinterpret_cast<float2*>(out + (size_t)row * HDIM + col) = o0;
            *reinterpret_cast<float2*>(out + (size_t)(row + 8) * HDIM + col) = o1;
        }
    }
}

extern "C" void kernel_launch(void* const* d_in, const int* in_sizes, int n_in,
                              void* d_out, int out_size)
{
    const float* x    = (const float*)d_in[0];
    const float* y    = (const float*)d_in[1];
    const float* fc1w = (const float*)d_in[2];
    const float* fc1b = (const float*)d_in[3];
    float* out = (float*)d_out;

    unsigned short* xattn_h = nullptr;
    cudaGetSymbolAddress((void**)&xattn_h, g_xattn_h);

    attn_kernel<<<BT / PAIRS_PER_BLK, 256>>>(x, y, xattn_h);

    const int smem_bytes = 2 * 128 * SP2 * (int)sizeof(unsigned);  // 45056
    cudaFuncSetAttribute(gemm_kernel,
                         cudaFuncAttributeMaxDynamicSharedMemorySize, smem_bytes);
    gemm_kernel<<<dim3(HDIM / 128, BT / 128), 256, smem_bytes>>>(
        xattn_h, fc1w, fc1b, out);
}